// round 1
// baseline (speedup 1.0000x reference)
#include <cuda_runtime.h>
#include <cuda_bf16.h>
#include <math.h>

// Problem constants
#define BV 32000
#define DD 1024
#define HH 16
#define LL 4
#define BB 2
#define SS 1024
#define HD 64
#define MM (BB*SS)   // 2048 rows

// ---------------- scratch (device globals; no allocation allowed) ----------------
__device__ float g_x[MM*DD];
__device__ float g_q[MM*DD];
__device__ float g_k[MM*DD];
__device__ float g_v[MM*DD];
__device__ float g_ctx[MM*DD];
__device__ float g_attn[MM*DD];

// ---------------- embedding + sinusoidal positional encoding ----------------
__global__ void embed_kernel(const int* __restrict__ tokens,
                             const float* __restrict__ emb,
                             float* __restrict__ x) {
    int row = blockIdx.x;              // 0..MM-1
    int s = row % SS;
    int tok = tokens[row];
    int tid = threadIdx.x;             // 256 threads
#pragma unroll
    for (int i = 0; i < 4; i++) {
        int d = tid + i * 256;
        int ii = d >> 1;
        float div = expf((float)(2 * ii) * (-9.210340371976184f / (float)DD));
        float ang = (float)s * div;
        float pe = (d & 1) ? cosf(ang) : sinf(ang);
        x[(size_t)row * DD + d] = emb[(size_t)tok * DD + d] + pe;
    }
}

// ---------------- fp32 SGEMM: C[M,N] = A[M,K] @ W[K,N] + bias[N] ----------------
// BM=128, BN=128, BK=8, 256 threads, 8x8 per thread. All dims divisible.
#define BM 128
#define BN 128
#define BK 8
#define TM 8
#define TN 8

__global__ __launch_bounds__(256)
void sgemm_bias(const float* __restrict__ A, const float* __restrict__ W,
                const float* __restrict__ bias, float* __restrict__ C,
                int M, int N, int K) {
    __shared__ float As[BK][BM];
    __shared__ float Bs[BK][BN];
    int bx = blockIdx.x;   // N tile
    int by = blockIdx.y;   // M tile
    int tid = threadIdx.x;
    int tx = tid % 16;     // 16x16 thread grid
    int ty = tid / 16;

    float acc[TM][TN];
#pragma unroll
    for (int i = 0; i < TM; i++)
#pragma unroll
        for (int j = 0; j < TN; j++) acc[i][j] = 0.f;

    // A loads: 128 rows x 8 cols = 256 float4 (2 per row)
    int aRow = tid >> 1;
    int aCol = (tid & 1) * 4;
    // B loads: 8 rows x 128 cols = 256 float4
    int bRow = tid >> 5;
    int bCol = (tid & 31) * 4;

    const float* Aptr = A + (size_t)by * BM * K;
    const float* Wptr = W + (size_t)bx * BN;

    for (int k0 = 0; k0 < K; k0 += BK) {
        float4 a4 = *(const float4*)(Aptr + (size_t)aRow * K + k0 + aCol);
        As[aCol + 0][aRow] = a4.x;
        As[aCol + 1][aRow] = a4.y;
        As[aCol + 2][aRow] = a4.z;
        As[aCol + 3][aRow] = a4.w;
        float4 b4 = *(const float4*)(Wptr + (size_t)(k0 + bRow) * N + bCol);
        *(float4*)&Bs[bRow][bCol] = b4;
        __syncthreads();
#pragma unroll
        for (int kk = 0; kk < BK; kk++) {
            float ar[TM], br[TN];
#pragma unroll
            for (int i = 0; i < TM; i++) ar[i] = As[kk][ty * TM + i];
#pragma unroll
            for (int j = 0; j < TN; j++) br[j] = Bs[kk][tx * TN + j];
#pragma unroll
            for (int i = 0; i < TM; i++)
#pragma unroll
                for (int j = 0; j < TN; j++)
                    acc[i][j] += ar[i] * br[j];
        }
        __syncthreads();
    }

#pragma unroll
    for (int i = 0; i < TM; i++) {
        int row = by * BM + ty * TM + i;
#pragma unroll
        for (int j = 0; j < TN; j += 4) {
            int col = bx * BN + tx * TN + j;
            float4 o;
            o.x = acc[i][j + 0] + bias[col + 0];
            o.y = acc[i][j + 1] + bias[col + 1];
            o.z = acc[i][j + 2] + bias[col + 2];
            o.w = acc[i][j + 3] + bias[col + 3];
            *(float4*)&C[(size_t)row * N + col] = o;
        }
    }
}

// ---------------- fused causal attention: one block per (b, h, q_row) ----------------
// q/k/v layout: [B, S, H, HD] contiguous == [B, S, D]
__global__ __launch_bounds__(128)
void attn_kernel(const float* __restrict__ q, const float* __restrict__ k,
                 const float* __restrict__ v, float* __restrict__ ctx) {
    int s_q = blockIdx.x;
    int h   = blockIdx.y;
    int b   = blockIdx.z;
    int tid = threadIdx.x;   // 128 threads

    __shared__ float qs[HD];
    __shared__ float p[SS];
    __shared__ float red[128];

    const float* qrow = q + ((size_t)(b * SS + s_q) * DD) + h * HD;
    if (tid < HD) qs[tid] = qrow[tid];
    __syncthreads();

    int nk = s_q + 1;
    float lmax = -1e30f;
    for (int j = tid; j < nk; j += 128) {
        const float* krow = k + ((size_t)(b * SS + j) * DD) + h * HD;
        float s = 0.f;
#pragma unroll
        for (int d = 0; d < HD; d += 4) {
            float4 kk = *(const float4*)(krow + d);
            s += qs[d] * kk.x + qs[d + 1] * kk.y + qs[d + 2] * kk.z + qs[d + 3] * kk.w;
        }
        s *= 0.125f;   // 1/sqrt(64)
        p[j] = s;
        lmax = fmaxf(lmax, s);
    }
    red[tid] = lmax;
    __syncthreads();
    for (int off = 64; off > 0; off >>= 1) {
        if (tid < off) red[tid] = fmaxf(red[tid], red[tid + off]);
        __syncthreads();
    }
    float mx = red[0];
    __syncthreads();

    float lsum = 0.f;
    for (int j = tid; j < nk; j += 128) {
        float e = expf(p[j] - mx);
        p[j] = e;
        lsum += e;
    }
    red[tid] = lsum;
    __syncthreads();
    for (int off = 64; off > 0; off >>= 1) {
        if (tid < off) red[tid] += red[tid + off];
        __syncthreads();
    }
    float inv = 1.0f / red[0];
    __syncthreads();

    // ctx: 2 halves of threads split keys; each owns dim d = tid & 63
    int d = tid & 63;
    int half = tid >> 6;
    float acc = 0.f;
    for (int j = half; j < nk; j += 2) {
        acc += p[j] * v[((size_t)(b * SS + j) * DD) + h * HD + d];
    }
    red[tid] = acc;
    __syncthreads();
    if (tid < 64) {
        ctx[((size_t)(b * SS + s_q) * DD) + h * HD + d] = (red[tid] + red[tid + 64]) * inv;
    }
}

// ---------------- residual add + LayerNorm, in place on x ----------------
__global__ __launch_bounds__(256)
void addln_kernel(float* __restrict__ x, const float* __restrict__ attn,
                  const float* __restrict__ g, const float* __restrict__ bta) {
    int row = blockIdx.x;
    int tid = threadIdx.x;   // 256 threads, 4 elems each
    __shared__ float red[256];
    float* xr = x + (size_t)row * DD;
    const float* ar = attn + (size_t)row * DD;

    float vals[4];
    float lsum = 0.f;
#pragma unroll
    for (int i = 0; i < 4; i++) {
        int d = tid + i * 256;
        vals[i] = xr[d] + ar[d];
        lsum += vals[i];
    }
    red[tid] = lsum;
    __syncthreads();
    for (int off = 128; off > 0; off >>= 1) {
        if (tid < off) red[tid] += red[tid + off];
        __syncthreads();
    }
    float mean = red[0] / (float)DD;
    __syncthreads();

    float lvar = 0.f;
#pragma unroll
    for (int i = 0; i < 4; i++) {
        float t = vals[i] - mean;
        lvar += t * t;
    }
    red[tid] = lvar;
    __syncthreads();
    for (int off = 128; off > 0; off >>= 1) {
        if (tid < off) red[tid] += red[tid + off];
        __syncthreads();
    }
    float rstd = rsqrtf(red[0] / (float)DD + 1e-5f);
#pragma unroll
    for (int i = 0; i < 4; i++) {
        int d = tid + i * 256;
        xr[d] = (vals[i] - mean) * rstd * g[d] + bta[d];
    }
}

// ---------------- launch ----------------
extern "C" void kernel_launch(void* const* d_in, const int* in_sizes, int n_in,
                              void* d_out, int out_size) {
    const int*   tokens = (const int*)  d_in[0];
    const float* emb    = (const float*)d_in[1];
    const float* qw     = (const float*)d_in[2];
    const float* qb     = (const float*)d_in[3];
    const float* kw     = (const float*)d_in[4];
    const float* kb     = (const float*)d_in[5];
    const float* vw     = (const float*)d_in[6];
    const float* vb     = (const float*)d_in[7];
    const float* ow     = (const float*)d_in[8];
    const float* ob     = (const float*)d_in[9];
    const float* ln_g   = (const float*)d_in[10];
    const float* ln_b   = (const float*)d_in[11];
    const float* out_w  = (const float*)d_in[12];
    const float* out_b  = (const float*)d_in[13];
    float* out = (float*)d_out;

    float *gx, *gq, *gk, *gv, *gctx, *gattn;
    cudaGetSymbolAddress((void**)&gx,    g_x);
    cudaGetSymbolAddress((void**)&gq,    g_q);
    cudaGetSymbolAddress((void**)&gk,    g_k);
    cudaGetSymbolAddress((void**)&gv,    g_v);
    cudaGetSymbolAddress((void**)&gctx,  g_ctx);
    cudaGetSymbolAddress((void**)&gattn, g_attn);

    embed_kernel<<<MM, 256>>>(tokens, emb, gx);

    dim3 gemmD(DD / BN, MM / BM);          // 8 x 16 blocks for D-sized GEMMs
    dim3 attnG(SS, HH, BB);

    for (int l = 0; l < LL; l++) {
        const float* qwl = qw + (size_t)l * DD * DD;
        const float* kwl = kw + (size_t)l * DD * DD;
        const float* vwl = vw + (size_t)l * DD * DD;
        const float* owl = ow + (size_t)l * DD * DD;
        sgemm_bias<<<gemmD, 256>>>(gx, qwl, qb + l * DD, gq, MM, DD, DD);
        sgemm_bias<<<gemmD, 256>>>(gx, kwl, kb + l * DD, gk, MM, DD, DD);
        sgemm_bias<<<gemmD, 256>>>(gx, vwl, vb + l * DD, gv, MM, DD, DD);
        attn_kernel<<<attnG, 128>>>(gq, gk, gv, gctx);
        sgemm_bias<<<gemmD, 256>>>(gctx, owl, ob + l * DD, gattn, MM, DD, DD);
        addln_kernel<<<MM, 256>>>(gx, gattn, ln_g + l * DD, ln_b + l * DD);
    }

    dim3 gemmV(BV / BN, MM / BM);          // 250 x 16 blocks
    sgemm_bias<<<gemmV, 256>>>(gx, out_w, out_b, out, MM, BV, DD);
}

// round 14
// speedup vs baseline: 2.2733x; 2.2733x over previous
#include <cuda_runtime.h>
#include <cuda_bf16.h>
#include <math.h>
#include <stdint.h>

// ---------------- problem constants ----------------
#define BV 32000
#define DD 1024
#define HH 16
#define LL 4
#define BB 2
#define SS 1024
#define HD 64
#define MM (BB*SS)   // 2048 rows

// transposed/split weight layout (element offsets)
#define WQKV_OFF 0                         // L blocks of [3072][1024]
#define WO_OFF   (LL*3*DD*DD)              // 12,582,912
#define WOUT_OFF (WO_OFF + LL*DD*DD)       // 16,777,216
#define WTOTAL   (WOUT_OFF + (size_t)BV*DD)  // 49,545,216

// ---------------- scratch (device globals) ----------------
__device__ __align__(16) float g_x[MM*DD];
__device__ __align__(16) __nv_bfloat16 g_xhi[MM*DD];
__device__ __align__(16) __nv_bfloat16 g_xlo[MM*DD];
__device__ __align__(16) float g_qkv[MM*3*DD];
__device__ __align__(16) __nv_bfloat16 g_ctxhi[MM*DD];
__device__ __align__(16) __nv_bfloat16 g_ctxlo[MM*DD];
__device__ __align__(16) float g_attn[MM*DD];
__device__ __align__(16) __nv_bfloat16 g_wT_hi[WTOTAL];
__device__ __align__(16) __nv_bfloat16 g_wT_lo[WTOTAL];
__device__ __align__(16) float g_bqkv[LL*3*DD];

// ---------------- helpers ----------------
__device__ __forceinline__ uint32_t smem_u32(const void* p) {
    uint32_t a;
    asm("{ .reg .u64 t; cvta.to.shared.u64 t, %1; cvt.u32.u64 %0, t; }" : "=r"(a) : "l"(p));
    return a;
}

__device__ __forceinline__ void split_bf16(float v, __nv_bfloat16& h, __nv_bfloat16& l) {
    h = __float2bfloat16(v);
    l = __float2bfloat16(v - __bfloat162float(h));
}

__device__ __forceinline__ void ldm_x4(uint32_t* r, uint32_t addr) {
    asm volatile("ldmatrix.sync.aligned.m8n8.x4.shared.b16 {%0,%1,%2,%3}, [%4];"
                 : "=r"(r[0]), "=r"(r[1]), "=r"(r[2]), "=r"(r[3]) : "r"(addr));
}
__device__ __forceinline__ void ldm_x2(uint32_t* r, uint32_t addr) {
    asm volatile("ldmatrix.sync.aligned.m8n8.x2.shared.b16 {%0,%1}, [%2];"
                 : "=r"(r[0]), "=r"(r[1]) : "r"(addr));
}
__device__ __forceinline__ void mma_bf16(float* c, const uint32_t* a, const uint32_t* b) {
    asm volatile("mma.sync.aligned.m16n8k16.row.col.f32.bf16.bf16.f32 "
                 "{%0,%1,%2,%3}, {%4,%5,%6,%7}, {%8,%9}, {%0,%1,%2,%3};"
                 : "+f"(c[0]), "+f"(c[1]), "+f"(c[2]), "+f"(c[3])
                 : "r"(a[0]), "r"(a[1]), "r"(a[2]), "r"(a[3]), "r"(b[0]), "r"(b[1]));
}
__device__ __forceinline__ void cpasync16(uint32_t saddr, const void* gaddr) {
    asm volatile("cp.async.cg.shared.global [%0], [%1], 16;" :: "r"(saddr), "l"(gaddr));
}
#define CP_COMMIT() asm volatile("cp.async.commit_group;" ::: "memory")
#define CP_WAIT1()  asm volatile("cp.async.wait_group 1;" ::: "memory")
#define CP_WAIT0()  asm volatile("cp.async.wait_group 0;" ::: "memory")

// ---------------- weight transpose + bf16 split: W[K][N] -> WT[N][K] hi/lo ----------------
__global__ __launch_bounds__(256)
void transpose_conv(const float* __restrict__ W, __nv_bfloat16* __restrict__ hi,
                    __nv_bfloat16* __restrict__ lo, int K, int N) {
    __shared__ float t[32][33];
    int n0 = blockIdx.x * 32, k0 = blockIdx.y * 32;
    int tx = threadIdx.x & 31, ty = threadIdx.x >> 5;   // 32 x 8
#pragma unroll
    for (int i = 0; i < 4; i++) {
        int k = k0 + ty + i * 8;
        t[ty + i * 8][tx] = W[(size_t)k * N + n0 + tx];
    }
    __syncthreads();
#pragma unroll
    for (int i = 0; i < 4; i++) {
        int n = n0 + ty + i * 8;
        float v = t[tx][ty + i * 8];
        __nv_bfloat16 h, l;
        split_bf16(v, h, l);
        hi[(size_t)n * K + k0 + tx] = h;
        lo[(size_t)n * K + k0 + tx] = l;
    }
}

__global__ void concat_bias(const float* __restrict__ qb, const float* __restrict__ kb,
                            const float* __restrict__ vb, float* __restrict__ o) {
    int l = blockIdx.y;
    int i = blockIdx.x * 256 + threadIdx.x;   // 0..1023
    o[l * 3 * DD + i]          = qb[l * DD + i];
    o[l * 3 * DD + DD + i]     = kb[l * DD + i];
    o[l * 3 * DD + 2 * DD + i] = vb[l * DD + i];
}

// ---------------- embedding + positional encoding (emits fp32 + bf16 hi/lo) ----------------
__global__ void embed_kernel(const int* __restrict__ tokens, const float* __restrict__ emb,
                             float* __restrict__ x, __nv_bfloat16* __restrict__ xhi,
                             __nv_bfloat16* __restrict__ xlo) {
    int row = blockIdx.x;
    int s = row % SS;
    int tok = tokens[row];
    int tid = threadIdx.x;
#pragma unroll
    for (int i = 0; i < 4; i++) {
        int d = tid + i * 256;
        int ii = d >> 1;
        float div = expf((float)(2 * ii) * (-9.210340371976184f / (float)DD));
        float ang = (float)s * div;
        float pe = (d & 1) ? cosf(ang) : sinf(ang);
        float v = emb[(size_t)tok * DD + d] + pe;
        size_t idx = (size_t)row * DD + d;
        x[idx] = v;
        __nv_bfloat16 h, l;
        split_bf16(v, h, l);
        xhi[idx] = h;
        xlo[idx] = l;
    }
}

// ---------------- split-bf16 GEMM via mma.sync + cp.async 2-stage pipeline ----------------
// C[M,N] = (Ahi+Alo)(Bhi+Blo)^T + bias. A: [M][K] bf16 K-major, B: [N][K] bf16 K-major.
// CTA tile 128x128x64, 8 warps (2M x 4N), warp tile 64x32 = 4x4 m16n8k16 frags.
#define STAGE_BYTES 65536
#define GSMEM_BYTES (2*STAGE_BYTES + 1024)

__global__ __launch_bounds__(256)
void gemm_tc(const __nv_bfloat16* __restrict__ Ahi, const __nv_bfloat16* __restrict__ Alo,
             const __nv_bfloat16* __restrict__ Bhi, const __nv_bfloat16* __restrict__ Blo,
             const float* __restrict__ bias, float* __restrict__ C, int N, int K) {
    extern __shared__ char dsmem[];
    uint32_t sb_raw = smem_u32(dsmem);
    uint32_t sb = (sb_raw + 1023u) & ~1023u;
    const uint32_t OFF_AHI = 0, OFF_ALO = 16384, OFF_BHI = 32768, OFF_BLO = 49152;

    int tid = threadIdx.x, lane = tid & 31, wid = tid >> 5;
    int wm = wid & 1, wn = wid >> 1;     // 2 x 4 warp grid

    size_t aoff = (size_t)blockIdx.y * 128 * K;
    size_t boff = (size_t)blockIdx.x * 128 * K;
    const __nv_bfloat16* srcs[4] = { Ahi + aoff, Alo + aoff, Bhi + boff, Blo + boff };
    const uint32_t offs[4] = { OFF_AHI, OFF_ALO, OFF_BHI, OFF_BLO };

    // per-thread fill addresses (same for every chunk): 4 uint4 per tile
    int frow[4], fq[4];
    uint32_t fo[4];
#pragma unroll
    for (int j = 0; j < 4; j++) {
        int u = j * 256 + tid;         // 1024 16B-units per tile
        frow[j] = u >> 3; fq[j] = u & 7;
        uint32_t o = (uint32_t)(frow[j] * 128 + fq[j] * 16);
        o ^= (o >> 3) & 0x70;          // SW128 swizzle
        fo[j] = o;
    }

    float acc[4][4][4];
#pragma unroll
    for (int mf = 0; mf < 4; mf++)
#pragma unroll
        for (int nf = 0; nf < 4; nf++)
#pragma unroll
            for (int i = 0; i < 4; i++) acc[mf][nf][i] = 0.f;

    int arow_l = (lane & 15);
    int aunit_l = (lane >> 4);
    int brow_l = (lane & 7);
    int bunit_l = ((lane >> 3) & 1);

    int nchunk = K >> 6;

    // prefetch chunk 0 into stage 0
    {
        uint32_t sbs = sb;
#pragma unroll
        for (int tl = 0; tl < 4; tl++) {
            const __nv_bfloat16* s = srcs[tl];
#pragma unroll
            for (int j = 0; j < 4; j++)
                cpasync16(sbs + offs[tl] + fo[j], s + (size_t)frow[j] * K + fq[j] * 8);
        }
        CP_COMMIT();
    }

    for (int c = 0; c < nchunk; c++) {
        int s = c & 1;
        uint32_t sbs = sb + (uint32_t)s * STAGE_BYTES;
        // prefetch chunk c+1 into the other stage (its last readers finished
        // at the __syncthreads ending iteration c-1)
        if (c + 1 < nchunk) {
            uint32_t sbn = sb + (uint32_t)(1 - s) * STAGE_BYTES;
#pragma unroll
            for (int tl = 0; tl < 4; tl++) {
                const __nv_bfloat16* src = srcs[tl] + (size_t)(c + 1) * 64;
#pragma unroll
                for (int j = 0; j < 4; j++)
                    cpasync16(sbn + offs[tl] + fo[j], src + (size_t)frow[j] * K + fq[j] * 8);
            }
            CP_COMMIT();
            CP_WAIT1();     // retire the group that filled stage s
        } else {
            CP_WAIT0();
        }
        __syncthreads();

        // ---- 4 k16 steps on stage s ----
#pragma unroll
        for (int ks = 0; ks < 4; ks++) {
            uint32_t ahi[4][4], alo[4][4];
#pragma unroll
            for (int mf = 0; mf < 4; mf++) {
                int row = wm * 64 + mf * 16 + arow_l;
                uint32_t o = (uint32_t)(row * 128 + (ks * 2 + aunit_l) * 16);
                o ^= (o >> 3) & 0x70;
                ldm_x4(ahi[mf], sbs + OFF_AHI + o);
                ldm_x4(alo[mf], sbs + OFF_ALO + o);
            }
            uint32_t bhi[4][2], blo[4][2];
#pragma unroll
            for (int nf = 0; nf < 4; nf++) {
                int row = wn * 32 + nf * 8 + brow_l;
                uint32_t o = (uint32_t)(row * 128 + (ks * 2 + bunit_l) * 16);
                o ^= (o >> 3) & 0x70;
                ldm_x2(bhi[nf], sbs + OFF_BHI + o);
                ldm_x2(blo[nf], sbs + OFF_BLO + o);
            }
#pragma unroll
            for (int mf = 0; mf < 4; mf++)
#pragma unroll
                for (int nf = 0; nf < 4; nf++) {
                    mma_bf16(acc[mf][nf], ahi[mf], bhi[nf]);
                    mma_bf16(acc[mf][nf], ahi[mf], blo[nf]);
                    mma_bf16(acc[mf][nf], alo[mf], bhi[nf]);
                }
        }
        __syncthreads();   // all warps done reading stage s before it is refilled
    }

    // ---- epilogue: direct register stores + bias ----
    size_t grow = (size_t)blockIdx.y * 128 + wm * 64;
    int gcol = blockIdx.x * 128 + wn * 32;
    int rl = lane >> 2;          // row within frag
    int cl = (lane & 3) * 2;     // col within frag
#pragma unroll
    for (int mf = 0; mf < 4; mf++) {
#pragma unroll
        for (int nf = 0; nf < 4; nf++) {
            int cc = gcol + nf * 8 + cl;
            float b0 = bias[cc], b1 = bias[cc + 1];
            size_t r0 = grow + mf * 16 + rl;
            float2 v0 = { acc[mf][nf][0] + b0, acc[mf][nf][1] + b1 };
            float2 v1 = { acc[mf][nf][2] + b0, acc[mf][nf][3] + b1 };
            *(float2*)&C[r0 * (size_t)N + cc] = v0;
            *(float2*)&C[(r0 + 8) * (size_t)N + cc] = v1;
        }
    }
}

// ---------------- q-tiled causal attention (qkv packed [M][3D]); emits ctx bf16 hi/lo ----------------
// One block per (b, h, 8 q-rows). 256 threads. K/V row loads reused across 8 queries.
#define QT 8
__global__ __launch_bounds__(256)
void attn_kernel(const float* __restrict__ qkv, __nv_bfloat16* __restrict__ ctxhi,
                 __nv_bfloat16* __restrict__ ctxlo) {
    int s0  = blockIdx.x * QT;
    int h   = blockIdx.y;
    int b   = blockIdx.z;
    int tid = threadIdx.x, lane = tid & 31, warp = tid >> 5;

    __shared__ float qs[QT][HD];        // 2 KB
    __shared__ float p[QT][SS];         // 32 KB
    __shared__ float wred[8][QT];       // per-warp partials
    __shared__ float mxs[QT], invs[QT];
    __shared__ float redc[256];

    const size_t rs = 3 * DD;

    // load 8 q rows into smem
    for (int i = tid; i < QT * HD; i += 256) {
        int r = i >> 6, d = i & 63;
        qs[r][d] = qkv[(size_t)(b * SS + s0 + r) * rs + h * HD + d];
    }
    __syncthreads();

    int nkmax = s0 + QT;

    // ---- pass 1: scores + per-thread max ----
    float lmax[QT];
#pragma unroll
    for (int r = 0; r < QT; r++) lmax[r] = -1e30f;

    for (int j = tid; j < nkmax; j += 256) {
        const float* krow = qkv + (size_t)(b * SS + j) * rs + DD + h * HD;
        float kr[HD];
#pragma unroll
        for (int d = 0; d < HD; d += 4) {
            float4 t = *(const float4*)(krow + d);
            kr[d] = t.x; kr[d + 1] = t.y; kr[d + 2] = t.z; kr[d + 3] = t.w;
        }
#pragma unroll
        for (int r = 0; r < QT; r++) {
            float s = 0.f;
#pragma unroll
            for (int d = 0; d < HD; d += 4) {
                float4 qv = *(const float4*)&qs[r][d];
                s += qv.x * kr[d] + qv.y * kr[d + 1] + qv.z * kr[d + 2] + qv.w * kr[d + 3];
            }
            s *= 0.125f;                 // 1/sqrt(64)
            if (j > s0 + r) s = -1e9f;   // causal mask
            p[r][j] = s;
            lmax[r] = fmaxf(lmax[r], s);
        }
    }
    // warp-shuffle max reduce, then 8-warp combine
#pragma unroll
    for (int r = 0; r < QT; r++) {
        float v = lmax[r];
#pragma unroll
        for (int off = 16; off > 0; off >>= 1)
            v = fmaxf(v, __shfl_xor_sync(0xffffffffu, v, off));
        if (lane == 0) wred[warp][r] = v;
    }
    __syncthreads();
    if (tid < QT) {
        float v = wred[0][tid];
#pragma unroll
        for (int w = 1; w < 8; w++) v = fmaxf(v, wred[w][tid]);
        mxs[tid] = v;
    }
    __syncthreads();

    // ---- pass 2: exp + per-thread sum ----
    float lsum[QT];
#pragma unroll
    for (int r = 0; r < QT; r++) lsum[r] = 0.f;
    for (int j = tid; j < nkmax; j += 256) {
#pragma unroll
        for (int r = 0; r < QT; r++) {
            float e = __expf(p[r][j] - mxs[r]);
            p[r][j] = e;
            lsum[r] += e;
        }
    }
#pragma unroll
    for (int r = 0; r < QT; r++) {
        float v = lsum[r];
#pragma unroll
        for (int off = 16; off > 0; off >>= 1)
            v += __shfl_xor_sync(0xffffffffu, v, off);
        if (lane == 0) wred[warp][r] = v;
    }
    __syncthreads();
    if (tid < QT) {
        float v = 0.f;
#pragma unroll
        for (int w = 0; w < 8; w++) v += wred[w][tid];
        invs[tid] = 1.0f / v;
    }
    __syncthreads();

    // ---- pass 3: ctx accumulation; V row load reused across 8 q-rows ----
    int d = tid & 63;
    int grp = tid >> 6;   // 4-way k-split
    float acc[QT];
#pragma unroll
    for (int r = 0; r < QT; r++) acc[r] = 0.f;
    for (int j = grp; j < nkmax; j += 4) {
        float v = qkv[(size_t)(b * SS + j) * rs + 2 * DD + h * HD + d];
#pragma unroll
        for (int r = 0; r < QT; r++) acc[r] += p[r][j] * v;
    }
#pragma unroll 1
    for (int r = 0; r < QT; r++) {
        redc[tid] = acc[r];
        __syncthreads();
        if (tid < 64) {
            float s = redc[d] + redc[64 + d] + redc[128 + d] + redc[192 + d];
            float val = s * invs[r];
            size_t idx = (size_t)(b * SS + s0 + r) * DD + h * HD + d;
            __nv_bfloat16 hh, ll;
            split_bf16(val, hh, ll);
            ctxhi[idx] = hh;
            ctxlo[idx] = ll;
        }
        __syncthreads();
    }
}

// ---------------- residual add + LayerNorm; emits fp32 x + bf16 hi/lo ----------------
__global__ __launch_bounds__(256)
void addln_kernel(float* __restrict__ x, const float* __restrict__ attn,
                  const float* __restrict__ g, const float* __restrict__ bta,
                  __nv_bfloat16* __restrict__ xhi, __nv_bfloat16* __restrict__ xlo) {
    int row = blockIdx.x;
    int tid = threadIdx.x;
    __shared__ float red[256];
    float* xr = x + (size_t)row * DD;
    const float* ar = attn + (size_t)row * DD;

    float vals[4];
    float lsum = 0.f;
#pragma unroll
    for (int i = 0; i < 4; i++) {
        int d = tid + i * 256;
        vals[i] = xr[d] + ar[d];
        lsum += vals[i];
    }
    red[tid] = lsum;
    __syncthreads();
    for (int off = 128; off > 0; off >>= 1) {
        if (tid < off) red[tid] += red[tid + off];
        __syncthreads();
    }
    float mean = red[0] / (float)DD;
    __syncthreads();

    float lvar = 0.f;
#pragma unroll
    for (int i = 0; i < 4; i++) {
        float t = vals[i] - mean;
        lvar += t * t;
    }
    red[tid] = lvar;
    __syncthreads();
    for (int off = 128; off > 0; off >>= 1) {
        if (tid < off) red[tid] += red[tid + off];
        __syncthreads();
    }
    float rstd = rsqrtf(red[0] / (float)DD + 1e-5f);
#pragma unroll
    for (int i = 0; i < 4; i++) {
        int d = tid + i * 256;
        float y = (vals[i] - mean) * rstd * g[d] + bta[d];
        xr[d] = y;
        __nv_bfloat16 h, l;
        split_bf16(y, h, l);
        xhi[(size_t)row * DD + d] = h;
        xlo[(size_t)row * DD + d] = l;
    }
}

// ---------------- launch ----------------
extern "C" void kernel_launch(void* const* d_in, const int* in_sizes, int n_in,
                              void* d_out, int out_size) {
    const int*   tokens = (const int*)  d_in[0];
    const float* emb    = (const float*)d_in[1];
    const float* qw     = (const float*)d_in[2];
    const float* qb     = (const float*)d_in[3];
    const float* kw     = (const float*)d_in[4];
    const float* kb     = (const float*)d_in[5];
    const float* vw     = (const float*)d_in[6];
    const float* vb     = (const float*)d_in[7];
    const float* ow     = (const float*)d_in[8];
    const float* ob     = (const float*)d_in[9];
    const float* ln_g   = (const float*)d_in[10];
    const float* ln_b   = (const float*)d_in[11];
    const float* out_w  = (const float*)d_in[12];
    const float* out_b  = (const float*)d_in[13];
    float* out = (float*)d_out;

    float *gx, *gqkv, *gattn, *gbqkv;
    __nv_bfloat16 *gxhi, *gxlo, *gctxhi, *gctxlo, *gwhi, *gwlo;
    cudaGetSymbolAddress((void**)&gx,     g_x);
    cudaGetSymbolAddress((void**)&gxhi,   g_xhi);
    cudaGetSymbolAddress((void**)&gxlo,   g_xlo);
    cudaGetSymbolAddress((void**)&gqkv,   g_qkv);
    cudaGetSymbolAddress((void**)&gctxhi, g_ctxhi);
    cudaGetSymbolAddress((void**)&gctxlo, g_ctxlo);
    cudaGetSymbolAddress((void**)&gattn,  g_attn);
    cudaGetSymbolAddress((void**)&gwhi,   g_wT_hi);
    cudaGetSymbolAddress((void**)&gwlo,   g_wT_lo);
    cudaGetSymbolAddress((void**)&gbqkv,  g_bqkv);

    cudaFuncSetAttribute(gemm_tc, cudaFuncAttributeMaxDynamicSharedMemorySize, GSMEM_BYTES);

    // ---- weight transpose + bf16 split (every call; graph-capturable) ----
    dim3 tgD(DD / 32, DD / 32);
    for (int l = 0; l < LL; l++) {
        size_t blk = (size_t)l * 3 * DD * DD;
        transpose_conv<<<tgD, 256>>>(qw + (size_t)l * DD * DD, gwhi + WQKV_OFF + blk,
                                     gwlo + WQKV_OFF + blk, DD, DD);
        transpose_conv<<<tgD, 256>>>(kw + (size_t)l * DD * DD, gwhi + WQKV_OFF + blk + (size_t)DD * DD,
                                     gwlo + WQKV_OFF + blk + (size_t)DD * DD, DD, DD);
        transpose_conv<<<tgD, 256>>>(vw + (size_t)l * DD * DD, gwhi + WQKV_OFF + blk + (size_t)2 * DD * DD,
                                     gwlo + WQKV_OFF + blk + (size_t)2 * DD * DD, DD, DD);
        transpose_conv<<<tgD, 256>>>(ow + (size_t)l * DD * DD, gwhi + WO_OFF + (size_t)l * DD * DD,
                                     gwlo + WO_OFF + (size_t)l * DD * DD, DD, DD);
    }
    transpose_conv<<<dim3(BV / 32, DD / 32), 256>>>(out_w, gwhi + WOUT_OFF, gwlo + WOUT_OFF, DD, BV);
    concat_bias<<<dim3(4, LL), 256>>>(qb, kb, vb, gbqkv);

    embed_kernel<<<MM, 256>>>(tokens, emb, gx, gxhi, gxlo);

    dim3 attnG(SS / QT, HH, BB);
    for (int l = 0; l < LL; l++) {
        size_t wblk = (size_t)l * 3 * DD * DD;
        // fused QKV: [2048,1024] x [1024,3072]
        gemm_tc<<<dim3(3 * DD / 128, MM / 128), 256, GSMEM_BYTES>>>(
            gxhi, gxlo, gwhi + WQKV_OFF + wblk, gwlo + WQKV_OFF + wblk,
            gbqkv + (size_t)l * 3 * DD, gqkv, 3 * DD, DD);
        attn_kernel<<<attnG, 256>>>(gqkv, gctxhi, gctxlo);
        gemm_tc<<<dim3(DD / 128, MM / 128), 256, GSMEM_BYTES>>>(
            gctxhi, gctxlo, gwhi + WO_OFF + (size_t)l * DD * DD, gwlo + WO_OFF + (size_t)l * DD * DD,
            ob + (size_t)l * DD, gattn, DD, DD);
        addln_kernel<<<MM, 256>>>(gx, gattn, ln_g + (size_t)l * DD, ln_b + (size_t)l * DD, gxhi, gxlo);
    }

    gemm_tc<<<dim3(BV / 128, MM / 128), 256, GSMEM_BYTES>>>(
        gxhi, gxlo, gwhi + WOUT_OFF, gwlo + WOUT_OFF, out_b, out, BV, DD);
}